// round 11
// baseline (speedup 1.0000x reference)
#include <cuda_runtime.h>
#include <stdint.h>

// EdgeFeaturizer R11: R10 pipeline with the s_cnt read/reset race fixed.
// Persistent blocks (888, occ 6), 4x8KB parity ring with full/empty mbarrier
// pairs; refills overlap the per-row tail; fully parallel expf epilogue.

#define N_ATOMS   8192
#define KNBR      12
#define NBINS     50
#define CAP       192
#define THREADS   256
#define T0        0.0035f
#define CHUNKS    4
#define CHUNK_F   2048          // floats per chunk (8 KB)
#define CHUNK_V   512           // float4 per chunk
#define GRID      888           // 148 SMs * 6 blocks resident

__device__ __forceinline__ unsigned smem_u32(const void* p) {
    return (unsigned)__cvta_generic_to_shared(p);
}

__device__ __forceinline__ void mbar_wait(unsigned mb, unsigned parity) {
    unsigned done;
    asm volatile(
        "{\n\t.reg .pred p;\n\t"
        "mbarrier.try_wait.parity.acquire.cta.shared::cta.b64 p, [%1], %2;\n\t"
        "selp.b32 %0, 1, 0, p;\n\t}"
        : "=r"(done) : "r"(mb), "r"(parity) : "memory");
    if (!done) {
        asm volatile(
            "{\n\t.reg .pred P1;\n\t"
            "WL_%=:\n\t"
            "mbarrier.try_wait.parity.acquire.cta.shared::cta.b64 P1, [%0], %1, 0x989680;\n\t"
            "@P1 bra.uni WD_%=;\n\t"
            "bra.uni WL_%=;\n\t"
            "WD_%=:\n\t}"
            :: "r"(mb), "r"(parity) : "memory");
    }
}

__device__ __forceinline__ void arm_slot(const float* __restrict__ dm,
                                         float* slot, unsigned full_mb,
                                         int row, int c) {
    const char* src = (const char*)(dm + (size_t)row * N_ATOMS + (size_t)c * CHUNK_F);
    asm volatile("mbarrier.arrive.expect_tx.shared.b64 _, [%0], %1;"
                 :: "r"(full_mb), "r"(CHUNK_F * 4) : "memory");
    asm volatile(
        "cp.async.bulk.shared::cta.global.mbarrier::complete_tx::bytes "
        "[%0], [%1], %2, [%3];"
        :: "r"(smem_u32(slot)), "l"(src), "r"(CHUNK_F * 4), "r"(full_mb) : "memory");
}

__global__ __launch_bounds__(THREADS, 6)
void edge_featurizer_kernel(const float* __restrict__ dm, float* __restrict__ out)
{
    __shared__ __align__(128) float ring[CHUNKS][CHUNK_F];    // 32 KB
    __shared__ unsigned long long cand[CAP];
    __shared__ int   s_cnt;
    __shared__ float s_d[KNBR];
    __shared__ int   s_i[KNBR];
    __shared__ __align__(8) unsigned long long s_full[CHUNKS];
    __shared__ __align__(8) unsigned long long s_empty[CHUNKS];

    const int tid = threadIdx.x;
    const int b   = blockIdx.x;

    if (tid == 0) {
        s_cnt = 0;
        #pragma unroll
        for (int c = 0; c < CHUNKS; c++) {
            asm volatile("mbarrier.init.shared.b64 [%0], 1;"
                         :: "r"(smem_u32(&s_full[c])) : "memory");
            asm volatile("mbarrier.init.shared.b64 [%0], 8;"
                         :: "r"(smem_u32(&s_empty[c])) : "memory");
        }
        // prologue: arm all 4 slots for this block's first row
        #pragma unroll
        for (int c = 0; c < CHUNKS; c++)
            arm_slot(dm, ring[c], smem_u32(&s_full[c]), b, c);
    }
    __syncthreads();          // inits (and arms) visible to all before any wait

    int k = 0;
    for (int r = b; r < N_ATOMS; r += GRID, k++) {
        const unsigned fp = (unsigned)(k & 1);

        // ---- chunk loop: wait full, scan, arrive empty, tid0 refills ----
        #pragma unroll
        for (int c = 0; c < CHUNKS; c++) {
            mbar_wait(smem_u32(&s_full[c]), fp);
            const float4* s4 = reinterpret_cast<const float4*>(ring[c]);
            const int i0 = tid;
            const int i1 = tid + THREADS;
            float4 v0 = s4[i0];
            float4 v1 = s4[i1];
            float m0 = fminf(fminf(v0.x, v0.y), fminf(v0.z, v0.w));
            float m1 = fminf(fminf(v1.x, v1.y), fminf(v1.z, v1.w));
            if (fminf(m0, m1) < T0) {                 // rare per-thread body
                #pragma unroll
                for (int j = 0; j < 2; j++) {
                    float4 v = (j == 0) ? v0 : v1;
                    int   li = (j == 0) ? i0 : i1;
                    int h = (v.x < T0) + (v.y < T0) + (v.z < T0) + (v.w < T0);
                    if (h) {
                        int p = atomicAdd(&s_cnt, h);
                        unsigned base = 4u * (unsigned)(c * CHUNK_V + li);
                        if (v.x < T0 && p < CAP)
                            cand[p++] = (((unsigned long long)__float_as_uint(v.x)) << 32) | (base + 0u);
                        if (v.y < T0 && p < CAP)
                            cand[p++] = (((unsigned long long)__float_as_uint(v.y)) << 32) | (base + 1u);
                        if (v.z < T0 && p < CAP)
                            cand[p++] = (((unsigned long long)__float_as_uint(v.z)) << 32) | (base + 2u);
                        if (v.w < T0 && p < CAP)
                            cand[p++] = (((unsigned long long)__float_as_uint(v.w)) << 32) | (base + 3u);
                    }
                }
            }
            __syncwarp();                              // all lanes done reading
            if ((tid & 31) == 0)
                asm volatile("mbarrier.arrive.shared.b64 _, [%0];"
                             :: "r"(smem_u32(&s_empty[c])) : "memory");
            if (tid == 0 && r + GRID < N_ATOMS) {
                // slot free once all 8 warps arrived (phase k)
                mbar_wait(smem_u32(&s_empty[c]), fp);
                arm_slot(dm, ring[c], smem_u32(&s_full[c]), r + GRID, c);
            }
        }
        __syncthreads();                   // all scans complete; s_cnt final
        int cc = s_cnt;
        __syncthreads();                   // ALL threads read cc before reset
        if (tid == 0) s_cnt = 0;           // visible via post-rank barrier

        // ---- exact fallback (rare): rescan this row from GLOBAL ----
        if (cc < KNBR || cc > CAP) {
            const float4* g4 = reinterpret_cast<const float4*>(dm + (size_t)r * N_ATOMS);
            float t = T0;
            while (cc < KNBR || cc > CAP) {
                t = (cc < KNBR) ? t * 8.0f : t * 0.25f;
                __syncthreads();
                if (tid == 0) s_cnt = 0;
                __syncthreads();
                for (int i = tid; i < N_ATOMS / 4; i += THREADS) {
                    float4 v = __ldg(g4 + i);
                    if (fminf(fminf(v.x, v.y), fminf(v.z, v.w)) < t) {
                        int h = (v.x < t) + (v.y < t) + (v.z < t) + (v.w < t);
                        int p = atomicAdd(&s_cnt, h);
                        unsigned base = 4u * (unsigned)i;
                        if (v.x < t && p < CAP)
                            cand[p++] = (((unsigned long long)__float_as_uint(v.x)) << 32) | (base + 0u);
                        if (v.y < t && p < CAP)
                            cand[p++] = (((unsigned long long)__float_as_uint(v.y)) << 32) | (base + 1u);
                        if (v.z < t && p < CAP)
                            cand[p++] = (((unsigned long long)__float_as_uint(v.z)) << 32) | (base + 2u);
                        if (v.w < t && p < CAP)
                            cand[p++] = (((unsigned long long)__float_as_uint(v.w)) << 32) | (base + 3u);
                    }
                }
                __syncthreads();
                cc = s_cnt;                // fenced on both sides
                __syncthreads();
                if (tid == 0) s_cnt = 0;
            }
        }

        // ---- parallel rank selection (keys unique -> ranks distinct) ----
        if (tid < cc) {
            unsigned long long mine = cand[tid];
            int rank = 0;
            int j = 0;
            for (; j + 4 <= cc; j += 4) {
                rank += (cand[j + 0] < mine);
                rank += (cand[j + 1] < mine);
                rank += (cand[j + 2] < mine);
                rank += (cand[j + 3] < mine);
            }
            for (; j < cc; j++) rank += (cand[j] < mine);
            if (rank < KNBR) {
                s_d[rank] = __uint_as_float((unsigned)(mine >> 32));
                s_i[rank] = (int)(mine & 0xffffffffu);
            }
        }
        __syncthreads();       // cand reads + s_cnt reset ordered before next row

        // ---- parallel output: edge_index + direct expf features ----
        if (tid < KNBR) {
            size_t eo = (size_t)r * (2 * KNBR) + 2 * tid;
            out[eo]     = (float)r;
            out[eo + 1] = (float)s_i[tid];
        }
        float* __restrict__ outF = out + (size_t)N_ATOMS * KNBR * 2
                                       + (size_t)r * (KNBR * NBINS);
        #pragma unroll
        for (int i = tid; i < KNBR * NBINS; i += THREADS) {
            int e = i / NBINS;
            int j = i - e * NBINS;
            float z = (s_d[e] - (float)j * (1.0f / 49.0f)) * 5.0f;  // /WIDTH
            outF[i] = __expf(-0.5f * z * z);
        }
        __syncthreads();       // s_d reads done before next row's rank writes
    }
}

extern "C" void kernel_launch(void* const* d_in, const int* in_sizes, int n_in,
                              void* d_out, int out_size)
{
    (void)in_sizes; (void)n_in; (void)out_size;
    const float* dm = (const float*)d_in[0];
    float* out = (float*)d_out;
    edge_featurizer_kernel<<<GRID, THREADS>>>(dm, out);
}

// round 12
// speedup vs baseline: 1.2662x; 1.2662x over previous
#include <cuda_runtime.h>
#include <stdint.h>

// EdgeFeaturizer R12: R9 structure (one row/block, fire-and-forget TMA staging,
// occ 6, parallel tail) with 8x4KB chunks for earlier scan start and finer
// wait/consume interleave.

#define N_ATOMS   8192
#define KNBR      12
#define NBINS     50
#define CAP       192
#define THREADS   256
#define T0        0.0035f
#define CHUNKS    8
#define CHUNK_F   1024          // floats per chunk (4 KB)
#define CHUNK_V   256           // float4 per chunk

__device__ __forceinline__ unsigned smem_u32(const void* p) {
    return (unsigned)__cvta_generic_to_shared(p);
}

__device__ __forceinline__ void mbar_wait0(unsigned mb) {
    unsigned done;
    asm volatile(
        "{\n\t.reg .pred p;\n\t"
        "mbarrier.try_wait.parity.acquire.cta.shared::cta.b64 p, [%1], 0;\n\t"
        "selp.b32 %0, 1, 0, p;\n\t}"
        : "=r"(done) : "r"(mb) : "memory");
    if (!done) {
        asm volatile(
            "{\n\t.reg .pred P1;\n\t"
            "WL_%=:\n\t"
            "mbarrier.try_wait.parity.acquire.cta.shared::cta.b64 P1, [%0], 0, 0x989680;\n\t"
            "@P1 bra.uni WD_%=;\n\t"
            "bra.uni WL_%=;\n\t"
            "WD_%=:\n\t}"
            :: "r"(mb) : "memory");
    }
}

__global__ __launch_bounds__(THREADS, 6)
void edge_featurizer_kernel(const float* __restrict__ dm, float* __restrict__ out)
{
    __shared__ __align__(128) float s_row[N_ATOMS];     // 32 KB row stage
    __shared__ unsigned long long cand[CAP];
    __shared__ int   s_cnt;
    __shared__ float s_d[KNBR];
    __shared__ int   s_i[KNBR];
    __shared__ __align__(8) unsigned long long s_mbar[CHUNKS];

    const int tid = threadIdx.x;
    const int row = blockIdx.x;

    if (tid == 0) {
        s_cnt = 0;
        #pragma unroll
        for (int c = 0; c < CHUNKS; c++)
            asm volatile("mbarrier.init.shared.b64 [%0], 1;"
                         :: "r"(smem_u32(&s_mbar[c])) : "memory");
    }
    __syncthreads();

    // ---- issue all 8 bulk copies up front (fire-and-forget) ----
    if (tid == 0) {
        const char* src = (const char*)(dm + (size_t)row * N_ATOMS);
        #pragma unroll
        for (int c = 0; c < CHUNKS; c++) {
            unsigned mb  = smem_u32(&s_mbar[c]);
            unsigned dst = smem_u32(&s_row[c * CHUNK_F]);
            asm volatile("mbarrier.arrive.expect_tx.shared.b64 _, [%0], %1;"
                         :: "r"(mb), "r"(CHUNK_F * 4) : "memory");
            asm volatile(
                "cp.async.bulk.shared::cta.global.mbarrier::complete_tx::bytes "
                "[%0], [%1], %2, [%3];"
                :: "r"(dst), "l"(src + (size_t)c * CHUNK_F * 4),
                   "r"(CHUNK_F * 4), "r"(mb) : "memory");
        }
    }

    const float4* s4 = reinterpret_cast<const float4*>(s_row);

    // ---- Phase 1: chunk-pipelined scan, one float4 per thread per chunk ----
    #pragma unroll
    for (int c = 0; c < CHUNKS; c++) {
        mbar_wait0(smem_u32(&s_mbar[c]));
        const int i = c * CHUNK_V + tid;
        float4 v = s4[i];
        float mn = fminf(fminf(v.x, v.y), fminf(v.z, v.w));
        if (mn < T0) {                                // rare per-thread body
            int h = (v.x < T0) + (v.y < T0) + (v.z < T0) + (v.w < T0);
            int p = atomicAdd(&s_cnt, h);
            unsigned base = 4u * (unsigned)i;
            if (v.x < T0 && p < CAP)
                cand[p++] = (((unsigned long long)__float_as_uint(v.x)) << 32) | (base + 0u);
            if (v.y < T0 && p < CAP)
                cand[p++] = (((unsigned long long)__float_as_uint(v.y)) << 32) | (base + 1u);
            if (v.z < T0 && p < CAP)
                cand[p++] = (((unsigned long long)__float_as_uint(v.z)) << 32) | (base + 2u);
            if (v.w < T0 && p < CAP)
                cand[p++] = (((unsigned long long)__float_as_uint(v.w)) << 32) | (base + 3u);
        }
    }
    __syncthreads();

    // ---- exact fallback: rescan from SMEM with adjusted t (rare) ----
    int c = s_cnt;
    float t = T0;
    while (c < KNBR || c > CAP) {
        t = (c < KNBR) ? t * 8.0f : t * 0.25f;
        __syncthreads();
        if (tid == 0) s_cnt = 0;
        __syncthreads();
        #pragma unroll
        for (int ii = 0; ii < N_ATOMS / 4 / THREADS; ii++) {
            int i = tid + ii * THREADS;
            float4 v = s4[i];
            if (fminf(fminf(v.x, v.y), fminf(v.z, v.w)) < t) {
                int h = (v.x < t) + (v.y < t) + (v.z < t) + (v.w < t);
                int p = atomicAdd(&s_cnt, h);
                unsigned base = 4u * (unsigned)i;
                if (v.x < t && p < CAP)
                    cand[p++] = (((unsigned long long)__float_as_uint(v.x)) << 32) | (base + 0u);
                if (v.y < t && p < CAP)
                    cand[p++] = (((unsigned long long)__float_as_uint(v.y)) << 32) | (base + 1u);
                if (v.z < t && p < CAP)
                    cand[p++] = (((unsigned long long)__float_as_uint(v.z)) << 32) | (base + 2u);
                if (v.w < t && p < CAP)
                    cand[p++] = (((unsigned long long)__float_as_uint(v.w)) << 32) | (base + 3u);
            }
        }
        __syncthreads();
        c = s_cnt;
        __syncthreads();
    }

    // ---- Phase 2: parallel rank selection (keys unique -> ranks distinct) ----
    if (tid < c) {
        unsigned long long mine = cand[tid];
        int rank = 0;
        int j = 0;
        for (; j + 4 <= c; j += 4) {
            rank += (cand[j + 0] < mine);
            rank += (cand[j + 1] < mine);
            rank += (cand[j + 2] < mine);
            rank += (cand[j + 3] < mine);
        }
        for (; j < c; j++) rank += (cand[j] < mine);
        if (rank < KNBR) {
            s_d[rank] = __uint_as_float((unsigned)(mine >> 32));
            s_i[rank] = (int)(mine & 0xffffffffu);
        }
    }
    __syncthreads();

    // ---- Phase 3: fully parallel output (no staging, direct expf) ----
    if (tid < KNBR) {
        size_t eo = (size_t)row * (2 * KNBR) + 2 * tid;
        out[eo]     = (float)row;
        out[eo + 1] = (float)s_i[tid];
    }
    float* __restrict__ outF = out + (size_t)N_ATOMS * KNBR * 2
                                   + (size_t)row * (KNBR * NBINS);
    #pragma unroll
    for (int i = tid; i < KNBR * NBINS; i += THREADS) {
        int e = i / NBINS;
        int j = i - e * NBINS;
        float z = (s_d[e] - (float)j * (1.0f / 49.0f)) * 5.0f;   // /WIDTH=0.2
        outF[i] = __expf(-0.5f * z * z);
    }
}

extern "C" void kernel_launch(void* const* d_in, const int* in_sizes, int n_in,
                              void* d_out, int out_size)
{
    (void)in_sizes; (void)n_in; (void)out_size;
    const float* dm = (const float*)d_in[0];
    float* out = (float*)d_out;
    edge_featurizer_kernel<<<N_ATOMS, THREADS>>>(dm, out);
}

// round 14
// speedup vs baseline: 1.2941x; 1.0221x over previous
#include <cuda_runtime.h>
#include <stdint.h>

// EdgeFeaturizer R13 (final): R9 structure — one row/block, 4x8KB fire-and-forget
// cp.async.bulk staging, occ 6, parallel rank selection, stage-free expf tail.
// At the measured LTS ceiling: 288.9 MB total traffic / ~6.3 TB/s ≈ 45.8 us.

#define N_ATOMS   8192
#define KNBR      12
#define NBINS     50
#define CAP       192
#define THREADS   256
#define T0        0.0035f
#define CHUNKS    4
#define CHUNK_F   2048          // floats per chunk (8 KB)
#define CHUNK_V   512           // float4 per chunk

__device__ __forceinline__ unsigned smem_u32(const void* p) {
    return (unsigned)__cvta_generic_to_shared(p);
}

__device__ __forceinline__ void mbar_wait0(unsigned mb) {
    unsigned done;
    asm volatile(
        "{\n\t.reg .pred p;\n\t"
        "mbarrier.try_wait.parity.acquire.cta.shared::cta.b64 p, [%1], 0;\n\t"
        "selp.b32 %0, 1, 0, p;\n\t}"
        : "=r"(done) : "r"(mb) : "memory");
    if (!done) {
        asm volatile(
            "{\n\t.reg .pred P1;\n\t"
            "WL_%=:\n\t"
            "mbarrier.try_wait.parity.acquire.cta.shared::cta.b64 P1, [%0], 0, 0x989680;\n\t"
            "@P1 bra.uni WD_%=;\n\t"
            "bra.uni WL_%=;\n\t"
            "WD_%=:\n\t}"
            :: "r"(mb) : "memory");
    }
}

__global__ __launch_bounds__(THREADS, 6)
void edge_featurizer_kernel(const float* __restrict__ dm, float* __restrict__ out)
{
    __shared__ __align__(128) float s_row[N_ATOMS];     // 32 KB row stage
    __shared__ unsigned long long cand[CAP];
    __shared__ int   s_cnt;
    __shared__ float s_d[KNBR];
    __shared__ int   s_i[KNBR];
    __shared__ __align__(8) unsigned long long s_mbar[CHUNKS];

    const int tid = threadIdx.x;
    const int row = blockIdx.x;

    if (tid == 0) {
        s_cnt = 0;
        #pragma unroll
        for (int c = 0; c < CHUNKS; c++)
            asm volatile("mbarrier.init.shared.b64 [%0], 1;"
                         :: "r"(smem_u32(&s_mbar[c])) : "memory");
    }
    __syncthreads();

    // ---- issue all 4 bulk copies up front (fire-and-forget TMA path) ----
    if (tid == 0) {
        const char* src = (const char*)(dm + (size_t)row * N_ATOMS);
        #pragma unroll
        for (int c = 0; c < CHUNKS; c++) {
            unsigned mb  = smem_u32(&s_mbar[c]);
            unsigned dst = smem_u32(&s_row[c * CHUNK_F]);
            asm volatile("mbarrier.arrive.expect_tx.shared.b64 _, [%0], %1;"
                         :: "r"(mb), "r"(CHUNK_F * 4) : "memory");
            asm volatile(
                "cp.async.bulk.shared::cta.global.mbarrier::complete_tx::bytes "
                "[%0], [%1], %2, [%3];"
                :: "r"(dst), "l"(src + (size_t)c * CHUNK_F * 4),
                   "r"(CHUNK_F * 4), "r"(mb) : "memory");
        }
    }

    const float4* s4 = reinterpret_cast<const float4*>(s_row);

    // ---- Phase 1: chunk-pipelined scan from SMEM ----
    #pragma unroll
    for (int c = 0; c < CHUNKS; c++) {
        mbar_wait0(smem_u32(&s_mbar[c]));
        const int i0 = c * CHUNK_V + tid;
        const int i1 = i0 + THREADS;
        float4 v0 = s4[i0];
        float4 v1 = s4[i1];
        float m0 = fminf(fminf(v0.x, v0.y), fminf(v0.z, v0.w));
        float m1 = fminf(fminf(v1.x, v1.y), fminf(v1.z, v1.w));
        if (fminf(m0, m1) < T0) {                     // rare per-thread body
            #pragma unroll
            for (int j = 0; j < 2; j++) {
                float4 v = (j == 0) ? v0 : v1;
                int    i = (j == 0) ? i0 : i1;
                int h = (v.x < T0) + (v.y < T0) + (v.z < T0) + (v.w < T0);
                if (h) {
                    int p = atomicAdd(&s_cnt, h);
                    unsigned base = 4u * (unsigned)i;
                    if (v.x < T0 && p < CAP)
                        cand[p++] = (((unsigned long long)__float_as_uint(v.x)) << 32) | (base + 0u);
                    if (v.y < T0 && p < CAP)
                        cand[p++] = (((unsigned long long)__float_as_uint(v.y)) << 32) | (base + 1u);
                    if (v.z < T0 && p < CAP)
                        cand[p++] = (((unsigned long long)__float_as_uint(v.z)) << 32) | (base + 2u);
                    if (v.w < T0 && p < CAP)
                        cand[p++] = (((unsigned long long)__float_as_uint(v.w)) << 32) | (base + 3u);
                }
            }
        }
    }
    __syncthreads();

    // ---- exact fallback: rescan from SMEM with adjusted t (rare) ----
    int c = s_cnt;
    float t = T0;
    while (c < KNBR || c > CAP) {
        t = (c < KNBR) ? t * 8.0f : t * 0.25f;
        __syncthreads();
        if (tid == 0) s_cnt = 0;
        __syncthreads();
        #pragma unroll
        for (int ii = 0; ii < N_ATOMS / 4 / THREADS; ii++) {
            int i = tid + ii * THREADS;
            float4 v = s4[i];
            if (fminf(fminf(v.x, v.y), fminf(v.z, v.w)) < t) {
                int h = (v.x < t) + (v.y < t) + (v.z < t) + (v.w < t);
                int p = atomicAdd(&s_cnt, h);
                unsigned base = 4u * (unsigned)i;
                if (v.x < t && p < CAP)
                    cand[p++] = (((unsigned long long)__float_as_uint(v.x)) << 32) | (base + 0u);
                if (v.y < t && p < CAP)
                    cand[p++] = (((unsigned long long)__float_as_uint(v.y)) << 32) | (base + 1u);
                if (v.z < t && p < CAP)
                    cand[p++] = (((unsigned long long)__float_as_uint(v.z)) << 32) | (base + 2u);
                if (v.w < t && p < CAP)
                    cand[p++] = (((unsigned long long)__float_as_uint(v.w)) << 32) | (base + 3u);
            }
        }
        __syncthreads();
        c = s_cnt;
        __syncthreads();
    }

    // ---- Phase 2: parallel rank selection (keys unique -> ranks distinct) ----
    if (tid < c) {
        unsigned long long mine = cand[tid];
        int rank = 0;
        int j = 0;
        for (; j + 4 <= c; j += 4) {
            rank += (cand[j + 0] < mine);
            rank += (cand[j + 1] < mine);
            rank += (cand[j + 2] < mine);
            rank += (cand[j + 3] < mine);
        }
        for (; j < c; j++) rank += (cand[j] < mine);
        if (rank < KNBR) {
            s_d[rank] = __uint_as_float((unsigned)(mine >> 32));
            s_i[rank] = (int)(mine & 0xffffffffu);
        }
    }
    __syncthreads();

    // ---- Phase 3: fully parallel output (stage-free) ----
    if (tid < KNBR) {                          // one 64-bit store per edge
        float2 e = make_float2((float)row, (float)s_i[tid]);
        reinterpret_cast<float2*>(out)[(size_t)row * KNBR + tid] = e;
    }
    float* __restrict__ outF = out + (size_t)N_ATOMS * KNBR * 2
                                   + (size_t)row * (KNBR * NBINS);
    {
        // strength-reduced (e,j) tracking: tid stride 256 over 600 outputs
        int e = tid / NBINS;
        int j = tid - e * NBINS;
        #pragma unroll
        for (int i = tid; i < KNBR * NBINS; i += THREADS) {
            float z = (s_d[e] - (float)j * (1.0f / 49.0f)) * 5.0f;  // /WIDTH=0.2
            outF[i] = __expf(-0.5f * z * z);
            j += THREADS - 5 * NBINS;          // 256 = 5*50 + 6
            e += 5;
            if (j >= NBINS) { j -= NBINS; e += 1; }
            else if (j < 0) { j += NBINS; e -= 1; }
        }
    }
}

extern "C" void kernel_launch(void* const* d_in, const int* in_sizes, int n_in,
                              void* d_out, int out_size)
{
    (void)in_sizes; (void)n_in; (void)out_size;
    const float* dm = (const float*)d_in[0];
    float* out = (float*)d_out;
    edge_featurizer_kernel<<<N_ATOMS, THREADS>>>(dm, out);
}

// round 15
// speedup vs baseline: 1.3011x; 1.0054x over previous
#include <cuda_runtime.h>
#include <stdint.h>

// EdgeFeaturizer R13 (final): R9 structure — one row/block, 4x8KB fire-and-forget
// cp.async.bulk staging, occ 6, parallel rank selection, stage-free expf tail.
// At the measured LTS ceiling: 288.9 MB total traffic / ~6.3 TB/s ≈ 45.8 us.

#define N_ATOMS   8192
#define KNBR      12
#define NBINS     50
#define CAP       192
#define THREADS   256
#define T0        0.0035f
#define CHUNKS    4
#define CHUNK_F   2048          // floats per chunk (8 KB)
#define CHUNK_V   512           // float4 per chunk

__device__ __forceinline__ unsigned smem_u32(const void* p) {
    return (unsigned)__cvta_generic_to_shared(p);
}

__device__ __forceinline__ void mbar_wait0(unsigned mb) {
    unsigned done;
    asm volatile(
        "{\n\t.reg .pred p;\n\t"
        "mbarrier.try_wait.parity.acquire.cta.shared::cta.b64 p, [%1], 0;\n\t"
        "selp.b32 %0, 1, 0, p;\n\t}"
        : "=r"(done) : "r"(mb) : "memory");
    if (!done) {
        asm volatile(
            "{\n\t.reg .pred P1;\n\t"
            "WL_%=:\n\t"
            "mbarrier.try_wait.parity.acquire.cta.shared::cta.b64 P1, [%0], 0, 0x989680;\n\t"
            "@P1 bra.uni WD_%=;\n\t"
            "bra.uni WL_%=;\n\t"
            "WD_%=:\n\t}"
            :: "r"(mb) : "memory");
    }
}

__global__ __launch_bounds__(THREADS, 6)
void edge_featurizer_kernel(const float* __restrict__ dm, float* __restrict__ out)
{
    __shared__ __align__(128) float s_row[N_ATOMS];     // 32 KB row stage
    __shared__ unsigned long long cand[CAP];
    __shared__ int   s_cnt;
    __shared__ float s_d[KNBR];
    __shared__ int   s_i[KNBR];
    __shared__ __align__(8) unsigned long long s_mbar[CHUNKS];

    const int tid = threadIdx.x;
    const int row = blockIdx.x;

    if (tid == 0) {
        s_cnt = 0;
        #pragma unroll
        for (int c = 0; c < CHUNKS; c++)
            asm volatile("mbarrier.init.shared.b64 [%0], 1;"
                         :: "r"(smem_u32(&s_mbar[c])) : "memory");
    }
    __syncthreads();

    // ---- issue all 4 bulk copies up front (fire-and-forget TMA path) ----
    if (tid == 0) {
        const char* src = (const char*)(dm + (size_t)row * N_ATOMS);
        #pragma unroll
        for (int c = 0; c < CHUNKS; c++) {
            unsigned mb  = smem_u32(&s_mbar[c]);
            unsigned dst = smem_u32(&s_row[c * CHUNK_F]);
            asm volatile("mbarrier.arrive.expect_tx.shared.b64 _, [%0], %1;"
                         :: "r"(mb), "r"(CHUNK_F * 4) : "memory");
            asm volatile(
                "cp.async.bulk.shared::cta.global.mbarrier::complete_tx::bytes "
                "[%0], [%1], %2, [%3];"
                :: "r"(dst), "l"(src + (size_t)c * CHUNK_F * 4),
                   "r"(CHUNK_F * 4), "r"(mb) : "memory");
        }
    }

    const float4* s4 = reinterpret_cast<const float4*>(s_row);

    // ---- Phase 1: chunk-pipelined scan from SMEM ----
    #pragma unroll
    for (int c = 0; c < CHUNKS; c++) {
        mbar_wait0(smem_u32(&s_mbar[c]));
        const int i0 = c * CHUNK_V + tid;
        const int i1 = i0 + THREADS;
        float4 v0 = s4[i0];
        float4 v1 = s4[i1];
        float m0 = fminf(fminf(v0.x, v0.y), fminf(v0.z, v0.w));
        float m1 = fminf(fminf(v1.x, v1.y), fminf(v1.z, v1.w));
        if (fminf(m0, m1) < T0) {                     // rare per-thread body
            #pragma unroll
            for (int j = 0; j < 2; j++) {
                float4 v = (j == 0) ? v0 : v1;
                int    i = (j == 0) ? i0 : i1;
                int h = (v.x < T0) + (v.y < T0) + (v.z < T0) + (v.w < T0);
                if (h) {
                    int p = atomicAdd(&s_cnt, h);
                    unsigned base = 4u * (unsigned)i;
                    if (v.x < T0 && p < CAP)
                        cand[p++] = (((unsigned long long)__float_as_uint(v.x)) << 32) | (base + 0u);
                    if (v.y < T0 && p < CAP)
                        cand[p++] = (((unsigned long long)__float_as_uint(v.y)) << 32) | (base + 1u);
                    if (v.z < T0 && p < CAP)
                        cand[p++] = (((unsigned long long)__float_as_uint(v.z)) << 32) | (base + 2u);
                    if (v.w < T0 && p < CAP)
                        cand[p++] = (((unsigned long long)__float_as_uint(v.w)) << 32) | (base + 3u);
                }
            }
        }
    }
    __syncthreads();

    // ---- exact fallback: rescan from SMEM with adjusted t (rare) ----
    int c = s_cnt;
    float t = T0;
    while (c < KNBR || c > CAP) {
        t = (c < KNBR) ? t * 8.0f : t * 0.25f;
        __syncthreads();
        if (tid == 0) s_cnt = 0;
        __syncthreads();
        #pragma unroll
        for (int ii = 0; ii < N_ATOMS / 4 / THREADS; ii++) {
            int i = tid + ii * THREADS;
            float4 v = s4[i];
            if (fminf(fminf(v.x, v.y), fminf(v.z, v.w)) < t) {
                int h = (v.x < t) + (v.y < t) + (v.z < t) + (v.w < t);
                int p = atomicAdd(&s_cnt, h);
                unsigned base = 4u * (unsigned)i;
                if (v.x < t && p < CAP)
                    cand[p++] = (((unsigned long long)__float_as_uint(v.x)) << 32) | (base + 0u);
                if (v.y < t && p < CAP)
                    cand[p++] = (((unsigned long long)__float_as_uint(v.y)) << 32) | (base + 1u);
                if (v.z < t && p < CAP)
                    cand[p++] = (((unsigned long long)__float_as_uint(v.z)) << 32) | (base + 2u);
                if (v.w < t && p < CAP)
                    cand[p++] = (((unsigned long long)__float_as_uint(v.w)) << 32) | (base + 3u);
            }
        }
        __syncthreads();
        c = s_cnt;
        __syncthreads();
    }

    // ---- Phase 2: parallel rank selection (keys unique -> ranks distinct) ----
    if (tid < c) {
        unsigned long long mine = cand[tid];
        int rank = 0;
        int j = 0;
        for (; j + 4 <= c; j += 4) {
            rank += (cand[j + 0] < mine);
            rank += (cand[j + 1] < mine);
            rank += (cand[j + 2] < mine);
            rank += (cand[j + 3] < mine);
        }
        for (; j < c; j++) rank += (cand[j] < mine);
        if (rank < KNBR) {
            s_d[rank] = __uint_as_float((unsigned)(mine >> 32));
            s_i[rank] = (int)(mine & 0xffffffffu);
        }
    }
    __syncthreads();

    // ---- Phase 3: fully parallel output (stage-free) ----
    if (tid < KNBR) {                          // one 64-bit store per edge
        float2 e = make_float2((float)row, (float)s_i[tid]);
        reinterpret_cast<float2*>(out)[(size_t)row * KNBR + tid] = e;
    }
    float* __restrict__ outF = out + (size_t)N_ATOMS * KNBR * 2
                                   + (size_t)row * (KNBR * NBINS);
    {
        // strength-reduced (e,j) tracking: tid stride 256 over 600 outputs
        int e = tid / NBINS;
        int j = tid - e * NBINS;
        #pragma unroll
        for (int i = tid; i < KNBR * NBINS; i += THREADS) {
            float z = (s_d[e] - (float)j * (1.0f / 49.0f)) * 5.0f;  // /WIDTH=0.2
            outF[i] = __expf(-0.5f * z * z);
            j += THREADS - 5 * NBINS;          // 256 = 5*50 + 6
            e += 5;
            if (j >= NBINS) { j -= NBINS; e += 1; }
            else if (j < 0) { j += NBINS; e -= 1; }
        }
    }
}

extern "C" void kernel_launch(void* const* d_in, const int* in_sizes, int n_in,
                              void* d_out, int out_size)
{
    (void)in_sizes; (void)n_in; (void)out_size;
    const float* dm = (const float*)d_in[0];
    float* out = (float*)d_out;
    edge_featurizer_kernel<<<N_ATOMS, THREADS>>>(dm, out);
}